// round 2
// baseline (speedup 1.0000x reference)
#include <cuda_runtime.h>
#include <cstdint>
#include <cstddef>

// Problem constants
constexpr int NN  = 8192;   // nodes
constexpr int FIN = 256;    // input features
constexpr int HH  = 64;     // hidden
constexpr int HC  = 128;    // fused hidden columns (h1 | h2)

// Scratch (device globals: allocation-free per harness rules)
__device__ float g_fts[NN * HC];      // [m][j] : j<64 -> seq1@W^T, j>=64 -> seq2@W^T
__device__ float g_h[NN * HC];        // [n][j] : h1 | h2 after bias+PReLU
__device__ float g_part[64 * 64];     // per-slab partial column sums of h1*msk
__device__ float g_mskpart[64];       // per-slab partial msk sums
__device__ float g_wc[64];            // disc_w @ sigmoid(c)

using u64 = unsigned long long;

__device__ __forceinline__ u64 pk2(float x, float y) {
    u64 r; asm("mov.b64 %0, {%1,%2};" : "=l"(r) : "f"(x), "f"(y)); return r;
}
__device__ __forceinline__ float2 unpk(u64 v) {
    float2 r; asm("mov.b64 {%0,%1}, %2;" : "=f"(r.x), "=f"(r.y) : "l"(v)); return r;
}
// Packed dual-FMA: 2x fp32 FMA per instruction on the fma pipe (PTX-only form).
__device__ __forceinline__ void fma2(u64& d, u64 a, u64 b) {
    asm("fma.rn.f32x2 %0, %1, %2, %0;" : "+l"(d) : "l"(a), "l"(b));
}

__device__ __forceinline__ void cpa16(void* dst, const void* src) {
    uint32_t d = (uint32_t)__cvta_generic_to_shared(dst);
    asm volatile("cp.async.ca.shared.global [%0], [%1], 16;\n" :: "r"(d), "l"(src));
}
__device__ __forceinline__ void cpa4(void* dst, const void* src) {
    uint32_t d = (uint32_t)__cvta_generic_to_shared(dst);
    asm volatile("cp.async.ca.shared.global [%0], [%1], 4;\n" :: "r"(d), "l"(src));
}
__device__ __forceinline__ void cp_commit() {
    asm volatile("cp.async.commit_group;\n" ::: "memory");
}
__device__ __forceinline__ void cp_wait0() {
    asm volatile("cp.async.wait_group 0;\n" ::: "memory");
}

// ---------------------------------------------------------------------------
// Kernel 1: fts[m, j] = (j<64 ? seq1 : seq2)[m,:] . fc_w[j&63, :]
// grid 512 blocks x 128 threads, 16 rows per block. fc_w chunk transposed in smem.
// ---------------------------------------------------------------------------
__global__ void __launch_bounds__(128) fts_kernel(
    const float* __restrict__ seq1, const float* __restrict__ seq2,
    const float* __restrict__ fcw) {
    __shared__ float wt[64][64];    // [f_local][h]  (transposed fc_w chunk)
    __shared__ float s1[16][64];    // seq1 rows, f chunk
    __shared__ float s2[16][64];

    const int tid = threadIdx.x;
    const int m0 = blockIdx.x * 16;
    const int jh = tid & 63;

    float acc[16];
#pragma unroll
    for (int r = 0; r < 16; ++r) acc[r] = 0.f;

    for (int fc = 0; fc < 4; ++fc) {
        const int f0 = fc * 64;
        __syncthreads();   // protect smem from previous chunk's readers
        // load+transpose fc_w chunk: fcw[row][f0 + c*4 ..]
        {
            const int row = tid & 63, half = tid >> 6;
#pragma unroll
            for (int p = 0; p < 8; ++p) {
                const int c = half * 8 + p;
                float4 v = *(const float4*)&fcw[row * FIN + f0 + c * 4];
                wt[c * 4 + 0][row] = v.x;
                wt[c * 4 + 1][row] = v.y;
                wt[c * 4 + 2][row] = v.z;
                wt[c * 4 + 3][row] = v.w;
            }
        }
        // load seq chunks
#pragma unroll
        for (int p = 0; p < 2; ++p) {
            const int idx = tid + 128 * p;
            const int r = idx >> 4, c4 = idx & 15;
            *(float4*)&s1[r][c4 * 4] = *(const float4*)&seq1[(size_t)(m0 + r) * FIN + f0 + c4 * 4];
            *(float4*)&s2[r][c4 * 4] = *(const float4*)&seq2[(size_t)(m0 + r) * FIN + f0 + c4 * 4];
        }
        __syncthreads();

        const float (*sp)[64] = (tid < 64) ? s1 : s2;   // uniform per warp
#pragma unroll 4
        for (int f = 0; f < 64; ++f) {
            const float wv = wt[f][jh];
#pragma unroll
            for (int r = 0; r < 16; ++r) acc[r] += sp[r][f] * wv;
        }
    }

#pragma unroll
    for (int r = 0; r < 16; ++r)
        g_fts[(size_t)(m0 + r) * HC + tid] = acc[r];
}

// ---------------------------------------------------------------------------
// Kernel 2 (dominant): h = PReLU(adj @ fts + bias)
// BM=32 x BN=128 tile per block, BK=32, 256 threads, 2x8 micro-tile in f32x2,
// cp.async double-buffered. grid = 256 blocks.
// ---------------------------------------------------------------------------
constexpr int BM = 32, BN = 128, BK = 32;

__global__ void __launch_bounds__(256) gemm_main(
    const float* __restrict__ adj,
    const float* __restrict__ bias,
    const float* __restrict__ alphap) {
    __shared__ __align__(16) float As[2][BK][BM + 2];   // [kk][r], pad 2 -> 8B-aligned pair reads
    __shared__ __align__(16) float Bs[2][BK][BN];

    const int tid = threadIdx.x;
    const int tx = tid & 15;        // n-tile position (8 cols each)
    const int ty = tid >> 4;        // m-tile position (2 rows each)
    const int n0 = blockIdx.x * BM;

    const int a_kk = tid & 31, a_r0 = tid >> 5;
    const int b_r0 = tid >> 5, b_c = (tid & 31) * 4;

    u64 acc[2][4];
#pragma unroll
    for (int i = 0; i < 2; ++i)
#pragma unroll
        for (int j = 0; j < 4; ++j) acc[i][j] = 0ull;

    const int NT = NN / BK;   // 256 k-chunks

    auto prefetch = [&](int t, int s) {
        const int k0 = t * BK;
#pragma unroll
        for (int p = 0; p < 4; ++p)
            cpa4(&As[s][a_kk][a_r0 + p * 8],
                 adj + (size_t)(n0 + a_r0 + p * 8) * NN + k0 + a_kk);
#pragma unroll
        for (int p = 0; p < 4; ++p)
            cpa16(&Bs[s][b_r0 + p * 8][b_c],
                  g_fts + (size_t)(k0 + b_r0 + p * 8) * HC + b_c);
    };

    prefetch(0, 0);
    cp_commit();

    for (int t = 0; t < NT; ++t) {
        const int s = t & 1;
        cp_wait0();
        __syncthreads();
        if (t + 1 < NT) { prefetch(t + 1, s ^ 1); cp_commit(); }

#pragma unroll 8
        for (int kk = 0; kk < BK; ++kk) {
            float2 a = *(const float2*)&As[s][kk][ty * 2];
            u64 A0 = pk2(a.x, a.x);
            u64 A1 = pk2(a.y, a.y);
            ulonglong2 bb0 = *(const ulonglong2*)&Bs[s][kk][tx * 8];
            ulonglong2 bb1 = *(const ulonglong2*)&Bs[s][kk][tx * 8 + 4];
            fma2(acc[0][0], A0, bb0.x); fma2(acc[0][1], A0, bb0.y);
            fma2(acc[0][2], A0, bb1.x); fma2(acc[0][3], A0, bb1.y);
            fma2(acc[1][0], A1, bb0.x); fma2(acc[1][1], A1, bb0.y);
            fma2(acc[1][2], A1, bb1.x); fma2(acc[1][3], A1, bb1.y);
        }
    }

    const float alpha = __ldg(alphap);
#pragma unroll
    for (int m = 0; m < 2; ++m) {
        const int n = n0 + ty * 2 + m;
#pragma unroll
        for (int p = 0; p < 4; ++p) {
            const int col = tx * 8 + p * 2;
            float2 v = unpk(acc[m][p]);
            v.x += __ldg(&bias[col & 63]);
            v.y += __ldg(&bias[(col + 1) & 63]);
            v.x = v.x > 0.f ? v.x : alpha * v.x;
            v.y = v.y > 0.f ? v.y : alpha * v.y;
            *(float2*)&g_h[(size_t)n * HC + col] = v;
        }
    }
}

// ---------------------------------------------------------------------------
// Kernel 3: deterministic partial reduction for c: per-128-row-slab column sums
// of h1 (cols 0..63) weighted by msk, plus msk partial sums. grid 64 x 256.
// ---------------------------------------------------------------------------
__global__ void __launch_bounds__(256) colsum_part(const float* __restrict__ msk) {
    __shared__ float sp[4][64];
    __shared__ float sm[256];
    const int b = blockIdx.x, tid = threadIdx.x;
    const int col = tid & 63, rg = tid >> 6;
    const int base = b * 128;

    float s = 0.f;
#pragma unroll 8
    for (int i = 0; i < 32; ++i) {
        const int n = base + rg + i * 4;
        s += msk[n] * g_h[(size_t)n * HC + col];
    }
    sp[rg][col] = s;
    sm[tid] = (tid < 128) ? msk[base + tid] : 0.f;
    __syncthreads();

    if (tid < 64)
        g_part[b * 64 + tid] = sp[0][tid] + sp[1][tid] + sp[2][tid] + sp[3][tid];

    for (int st = 128; st > 0; st >>= 1) {
        if (tid < st) sm[tid] += sm[tid + st];
        __syncthreads();
    }
    if (tid == 0) g_mskpart[b] = sm[0];
}

// ---------------------------------------------------------------------------
// Kernel 4: c = sigmoid(colsum / msksum); wc = disc_w @ c.  1 block x 64 thr.
// ---------------------------------------------------------------------------
__global__ void make_wc(const float* __restrict__ disc_w) {
    __shared__ float c[64];
    __shared__ float msum;
    const int j = threadIdx.x;

    float s = 0.f;
    for (int b = 0; b < 64; ++b) s += g_part[b * 64 + j];
    if (j == 0) {
        float m = 0.f;
        for (int b = 0; b < 64; ++b) m += g_mskpart[b];
        msum = m;
    }
    __syncthreads();
    float cv = s / msum;
    cv = 1.f / (1.f + expf(-cv));
    c[j] = cv;
    __syncthreads();

    float w = 0.f;
#pragma unroll
    for (int k = 0; k < 64; ++k) w += disc_w[j * 64 + k] * c[k];
    g_wc[j] = w;
}

// ---------------------------------------------------------------------------
// Kernel 5: out[n] = h1[n,:].wc + b ; out[N+n] = h2[n,:].wc + b
// warp per row. grid 1024 x 256.
// ---------------------------------------------------------------------------
__global__ void __launch_bounds__(256) scores(const float* __restrict__ db,
                                              float* __restrict__ out) {
    const int warp = threadIdx.x >> 5, lane = threadIdx.x & 31;
    const int n = blockIdx.x * 8 + warp;
    const float2* hp = (const float2*)(g_h + (size_t)n * HC);
    const float2 w2 = ((const float2*)g_wc)[lane];
    const float2 v1 = hp[lane];
    const float2 v2 = hp[32 + lane];
    float s1 = v1.x * w2.x + v1.y * w2.y;
    float s2 = v2.x * w2.x + v2.y * w2.y;
#pragma unroll
    for (int o = 16; o; o >>= 1) {
        s1 += __shfl_down_sync(0xffffffffu, s1, o);
        s2 += __shfl_down_sync(0xffffffffu, s2, o);
    }
    if (lane == 0) {
        const float bb = __ldg(db);
        out[n] = s1 + bb;
        out[NN + n] = s2 + bb;
    }
}

// ---------------------------------------------------------------------------
// Inputs (metadata order): seq1, seq2, adj, msk, fc_w, gcn_bias, prelu_alpha,
//                          disc_w, disc_b.   Output: [1, 2N] float32.
// ---------------------------------------------------------------------------
extern "C" void kernel_launch(void* const* d_in, const int* in_sizes, int n_in,
                              void* d_out, int out_size) {
    const float* seq1  = (const float*)d_in[0];
    const float* seq2  = (const float*)d_in[1];
    const float* adj   = (const float*)d_in[2];
    const float* msk   = (const float*)d_in[3];
    const float* fcw   = (const float*)d_in[4];
    const float* gbias = (const float*)d_in[5];
    const float* alpha = (const float*)d_in[6];
    const float* discw = (const float*)d_in[7];
    const float* discb = (const float*)d_in[8];
    float* out = (float*)d_out;

    fts_kernel<<<NN / 16, 128>>>(seq1, seq2, fcw);
    gemm_main<<<NN / BM, 256>>>(adj, gbias, alpha);
    colsum_part<<<64, 256>>>(msk);
    make_wc<<<1, 64>>>(discw);
    scores<<<NN / 8, 256>>>(discb, out);
}

// round 4
// speedup vs baseline: 3.8638x; 3.8638x over previous
#include <cuda_runtime.h>
#include <cstdint>
#include <cstddef>

// ---------------------------------------------------------------------------
// Problem constants
// ---------------------------------------------------------------------------
constexpr int NN  = 8192;   // nodes
constexpr int FIN = 256;    // input features
constexpr int HC  = 128;    // fused hidden columns (h1 | h2)

// GEMM tiling (mma.sync bf16, 3-pass error split)
constexpr int BM = 128, BN = 128, BKk = 32;
constexpr int KHALF = NN / 2;           // 4096
constexpr int NT = KHALF / BKk;         // 128 iters
constexpr int ROWB = 80;                // padded smem row stride (bytes): conflict-free
constexpr int OAH = 0;
constexpr int OAL = OAH + BM * ROWB;    // 10240
constexpr int OBH = OAL + BM * ROWB;    // 20480
constexpr int OBL = OBH + BN * ROWB;    // 30720
constexpr int STAGE = OBL + BN * ROWB;  // 40960 bytes / stage
constexpr int DYN_SMEM = 2 * STAGE + 256;

// ---------------------------------------------------------------------------
// Device scratch (allocation-free per harness rules)
// ---------------------------------------------------------------------------
__device__ unsigned short g_bhi[HC * NN];   // fts^T hi  [n][k] bf16
__device__ unsigned short g_blo[HC * NN];   // fts^T lo  [n][k] bf16
__device__ float g_acc0[NN * HC];           // K-half 0 partial
__device__ float g_acc1[NN * HC];           // K-half 1 partial
__device__ float g_h[NN * HC];              // h1|h2 after bias+PReLU
__device__ float g_part[64 * 64];
__device__ float g_mskpart[64];
__device__ float g_wc[64];

// ---------------------------------------------------------------------------
// Helpers (baseline PTX only — no sm_103a-specific features)
// ---------------------------------------------------------------------------
__device__ __forceinline__ uint32_t smem_u32(const void* p) {
    uint32_t r;
    asm("{ .reg .u64 t; cvta.to.shared.u64 t, %1; cvt.u32.u64 %0, t; }"
        : "=r"(r) : "l"(p));
    return r;
}
// packed bf16x2: high half = bf16(hi), low half = bf16(lo)
__device__ __forceinline__ uint32_t pkbf(float hi, float lo) {
    uint32_t r;
    asm("cvt.rn.bf16x2.f32 %0, %1, %2;" : "=r"(r) : "f"(hi), "f"(lo));
    return r;
}
__device__ __forceinline__ void sts128(uint32_t addr, uint32_t a, uint32_t b,
                                       uint32_t c, uint32_t d) {
    asm volatile("st.shared.v4.b32 [%0], {%1, %2, %3, %4};"
                 :: "r"(addr), "r"(a), "r"(b), "r"(c), "r"(d) : "memory");
}
__device__ __forceinline__ void ldm4(uint32_t* r, uint32_t addr) {
    asm volatile("ldmatrix.sync.aligned.m8n8.x4.shared.b16 {%0,%1,%2,%3}, [%4];"
                 : "=r"(r[0]), "=r"(r[1]), "=r"(r[2]), "=r"(r[3]) : "r"(addr));
}
__device__ __forceinline__ void mma16816(float* c, const uint32_t* a,
                                         uint32_t b0, uint32_t b1) {
    asm volatile(
        "mma.sync.aligned.m16n8k16.row.col.f32.bf16.bf16.f32 "
        "{%0,%1,%2,%3}, {%4,%5,%6,%7}, {%8,%9}, {%0,%1,%2,%3};"
        : "+f"(c[0]), "+f"(c[1]), "+f"(c[2]), "+f"(c[3])
        : "r"(a[0]), "r"(a[1]), "r"(a[2]), "r"(a[3]), "r"(b0), "r"(b1));
}

// ---------------------------------------------------------------------------
// Kernel 1: fts = seq@W^T (both seqs); emit bf16 hi/lo TRANSPOSED [n][k]
// ---------------------------------------------------------------------------
__global__ void __launch_bounds__(128) fts_kernel(
    const float* __restrict__ seq1, const float* __restrict__ seq2,
    const float* __restrict__ fcw) {
    __shared__ float wt[64][64];    // transposed fc_w chunk [f_local][h]
    __shared__ float s1[16][64];
    __shared__ float s2[16][64];

    const int tid = threadIdx.x;
    const int m0 = blockIdx.x * 16;
    const int jh = tid & 63;

    float acc[16];
#pragma unroll
    for (int r = 0; r < 16; ++r) acc[r] = 0.f;

    for (int fc = 0; fc < 4; ++fc) {
        const int f0 = fc * 64;
        __syncthreads();
        {
            const int row = tid & 63, half = tid >> 6;
#pragma unroll
            for (int p = 0; p < 8; ++p) {
                const int c = half * 8 + p;
                float4 v = *(const float4*)&fcw[row * FIN + f0 + c * 4];
                wt[c * 4 + 0][row] = v.x;
                wt[c * 4 + 1][row] = v.y;
                wt[c * 4 + 2][row] = v.z;
                wt[c * 4 + 3][row] = v.w;
            }
        }
#pragma unroll
        for (int p = 0; p < 2; ++p) {
            const int idx = tid + 128 * p;
            const int r = idx >> 4, c4 = idx & 15;
            *(float4*)&s1[r][c4 * 4] = *(const float4*)&seq1[(size_t)(m0 + r) * FIN + f0 + c4 * 4];
            *(float4*)&s2[r][c4 * 4] = *(const float4*)&seq2[(size_t)(m0 + r) * FIN + f0 + c4 * 4];
        }
        __syncthreads();

        const float (*sp)[64] = (tid < 64) ? s1 : s2;
#pragma unroll 4
        for (int f = 0; f < 64; ++f) {
            const float wv = wt[f][jh];
#pragma unroll
            for (int r = 0; r < 16; ++r) acc[r] += sp[r][f] * wv;
        }
    }

    // bf16 hi/lo split, transposed store: row = tid (n), cols k = m0..m0+15
#pragma unroll
    for (int r = 0; r < 16; r += 2) {
        const float v0 = acc[r], v1 = acc[r + 1];
        uint32_t h = pkbf(v1, v0);
        float f0 = __uint_as_float(h << 16);
        float f1 = __uint_as_float(h & 0xffff0000u);
        uint32_t l = pkbf(v1 - f1, v0 - f0);
        const size_t off = (size_t)tid * NN + m0 + r;
        *(uint32_t*)(g_bhi + off) = h;
        *(uint32_t*)(g_blo + off) = l;
    }
}

// ---------------------------------------------------------------------------
// Kernel 2 (dominant): HMMA bf16-split GEMM.
// CTA = (mi, kh): rows [mi*128, +128), K-half kh; 8 warps (4M x 2N), 2-stage.
// ---------------------------------------------------------------------------
__global__ void __launch_bounds__(256, 1)
gemm_mma(const float* __restrict__ adj) {
    extern __shared__ char dyn[];
    const uint32_t sbase = (smem_u32(dyn) + 127u) & ~127u;

    const int tid = threadIdx.x;
    const int wid = tid >> 5;
    const int lane = tid & 31;
    const int mi = blockIdx.x >> 1;
    const int kh = blockIdx.x & 1;
    const int m0 = mi * BM;
    const size_t kbase = (size_t)kh * KHALF;

    const int wm = (wid & 3) * 32;      // warp M offset
    const int wn = (wid >> 2) * 64;     // warp N offset

    // producer mapping: 256 threads -> (row 0..127, sel 0/1)
    const int lrow = tid & 127;
    const int lsel = tid >> 7;
    const float* aptr = adj + (size_t)(m0 + lrow) * NN + kbase + lsel * 16;
    const unsigned short* bsrc = (lsel ? g_blo : g_bhi) + (size_t)lrow * NN + kbase;
    const uint32_t a_sts = (uint32_t)(lrow * ROWB + lsel * 32);
    const uint32_t b_sts = (uint32_t)(lrow * ROWB);
    const uint32_t b_sts_off = lsel ? OBL : OBH;

    // ldmatrix per-lane offsets
    const uint32_t a_ld = (uint32_t)((wm + (lane & 15)) * ROWB + (lane >> 4) * 16);
    const uint32_t b_ld = (uint32_t)((wn + ((lane >> 4) << 3) + (lane & 7)) * ROWB
                                     + ((lane >> 3) & 1) * 16);

    float acc[2][8][4];
#pragma unroll
    for (int i = 0; i < 2; ++i)
#pragma unroll
        for (int j = 0; j < 8; ++j)
#pragma unroll
            for (int q = 0; q < 4; ++q) acc[i][j][q] = 0.f;

    float4 av[4];
    uint4 bv[4];

    auto LDGS = [&](int t) {
        const float4* ap = (const float4*)(aptr + (size_t)t * BKk);
#pragma unroll
        for (int j = 0; j < 4; ++j) av[j] = ap[j];
        const uint4* bp = (const uint4*)(bsrc + (size_t)t * BKk);
#pragma unroll
        for (int j = 0; j < 4; ++j) bv[j] = bp[j];
    };
    auto STS = [&](int s) {
        const uint32_t st = sbase + s * STAGE;
        uint32_t hw[8], lw[8];
#pragma unroll
        for (int j = 0; j < 4; ++j) {
            uint32_t h01 = pkbf(av[j].y, av[j].x);
            uint32_t h23 = pkbf(av[j].w, av[j].z);
            float f0 = __uint_as_float(h01 << 16);
            float f1 = __uint_as_float(h01 & 0xffff0000u);
            float f2 = __uint_as_float(h23 << 16);
            float f3 = __uint_as_float(h23 & 0xffff0000u);
            hw[2 * j] = h01; hw[2 * j + 1] = h23;
            lw[2 * j] = pkbf(av[j].y - f1, av[j].x - f0);
            lw[2 * j + 1] = pkbf(av[j].w - f3, av[j].z - f2);
        }
        sts128(st + OAH + a_sts,      hw[0], hw[1], hw[2], hw[3]);
        sts128(st + OAH + a_sts + 16, hw[4], hw[5], hw[6], hw[7]);
        sts128(st + OAL + a_sts,      lw[0], lw[1], lw[2], lw[3]);
        sts128(st + OAL + a_sts + 16, lw[4], lw[5], lw[6], lw[7]);
#pragma unroll
        for (int j = 0; j < 4; ++j)
            sts128(st + b_sts_off + b_sts + j * 16, bv[j].x, bv[j].y, bv[j].z, bv[j].w);
    };
    auto COMPUTE = [&](int s) {
        const uint32_t st = sbase + s * STAGE;
#pragma unroll
        for (int ks = 0; ks < 2; ++ks) {
            uint32_t ah[2][4], al[2][4];
#pragma unroll
            for (int i = 0; i < 2; ++i) {
                ldm4(ah[i], st + OAH + a_ld + i * (16 * ROWB) + ks * 32);
                ldm4(al[i], st + OAL + a_ld + i * (16 * ROWB) + ks * 32);
            }
#pragma unroll
            for (int jp = 0; jp < 4; ++jp) {
                uint32_t bh[4], bl[4];
                ldm4(bh, st + OBH + b_ld + jp * (16 * ROWB) + ks * 32);
                ldm4(bl, st + OBL + b_ld + jp * (16 * ROWB) + ks * 32);
                // pass-major to break accumulator RAW chains
                mma16816(acc[0][2 * jp],     ah[0], bh[0], bh[1]);
                mma16816(acc[0][2 * jp + 1], ah[0], bh[2], bh[3]);
                mma16816(acc[1][2 * jp],     ah[1], bh[0], bh[1]);
                mma16816(acc[1][2 * jp + 1], ah[1], bh[2], bh[3]);
                mma16816(acc[0][2 * jp],     ah[0], bl[0], bl[1]);
                mma16816(acc[0][2 * jp + 1], ah[0], bl[2], bl[3]);
                mma16816(acc[1][2 * jp],     ah[1], bl[0], bl[1]);
                mma16816(acc[1][2 * jp + 1], ah[1], bl[2], bl[3]);
                mma16816(acc[0][2 * jp],     al[0], bh[0], bh[1]);
                mma16816(acc[0][2 * jp + 1], al[0], bh[2], bh[3]);
                mma16816(acc[1][2 * jp],     al[1], bh[0], bh[1]);
                mma16816(acc[1][2 * jp + 1], al[1], bh[2], bh[3]);
            }
        }
    };

    LDGS(0);
    STS(0);
    __syncthreads();

    int s = 0;
    for (int t = 0; t < NT; ++t) {
        const bool more = (t + 1 < NT);
        if (more) LDGS(t + 1);
        COMPUTE(s);
        __syncthreads();
        if (more) STS(s ^ 1);
        __syncthreads();
        s ^= 1;
    }

    // epilogue: write partials
    float* gacc = (kh ? g_acc1 : g_acc0);
    const int r0 = m0 + wm + (lane >> 2);
    const int cb = wn + (lane & 3) * 2;
#pragma unroll
    for (int i = 0; i < 2; ++i) {
#pragma unroll
        for (int j = 0; j < 8; ++j) {
            const int row = r0 + i * 16;
            const int col = cb + j * 8;
            *(float2*)&gacc[(size_t)row * HC + col] =
                make_float2(acc[i][j][0], acc[i][j][1]);
            *(float2*)&gacc[(size_t)(row + 8) * HC + col] =
                make_float2(acc[i][j][2], acc[i][j][3]);
        }
    }
}

// ---------------------------------------------------------------------------
// Kernel 3: h = PReLU(acc0 + acc1 + bias)
// ---------------------------------------------------------------------------
__global__ void __launch_bounds__(256) epi_kernel(
    const float* __restrict__ bias, const float* __restrict__ alphap) {
    const int i = blockIdx.x * 256 + threadIdx.x;   // float4 index
    const float alpha = __ldg(alphap);
    const int c = (i & 31) * 4;
    const float4 b4 = *(const float4*)&bias[c & 63];
    float4 x = *((const float4*)g_acc0 + i);
    float4 y = *((const float4*)g_acc1 + i);
    float4 v;
    v.x = x.x + y.x + b4.x; v.x = v.x > 0.f ? v.x : alpha * v.x;
    v.y = x.y + y.y + b4.y; v.y = v.y > 0.f ? v.y : alpha * v.y;
    v.z = x.z + y.z + b4.z; v.z = v.z > 0.f ? v.z : alpha * v.z;
    v.w = x.w + y.w + b4.w; v.w = v.w > 0.f ? v.w : alpha * v.w;
    *((float4*)g_h + i) = v;
}

// ---------------------------------------------------------------------------
// Kernel 4: per-slab partial colsums of h1*msk + msk partials
// ---------------------------------------------------------------------------
__global__ void __launch_bounds__(256) colsum_part(const float* __restrict__ msk) {
    __shared__ float sp[4][64];
    __shared__ float sm[256];
    const int b = blockIdx.x, tid = threadIdx.x;
    const int col = tid & 63, rg = tid >> 6;
    const int base = b * 128;

    float s = 0.f;
#pragma unroll 8
    for (int i = 0; i < 32; ++i) {
        const int n = base + rg + i * 4;
        s += msk[n] * g_h[(size_t)n * HC + col];
    }
    sp[rg][col] = s;
    sm[tid] = (tid < 128) ? msk[base + tid] : 0.f;
    __syncthreads();

    if (tid < 64)
        g_part[b * 64 + tid] = sp[0][tid] + sp[1][tid] + sp[2][tid] + sp[3][tid];

    for (int st = 128; st > 0; st >>= 1) {
        if (tid < st) sm[tid] += sm[tid + st];
        __syncthreads();
    }
    if (tid == 0) g_mskpart[b] = sm[0];
}

// ---------------------------------------------------------------------------
// Kernel 5: c = sigmoid(colsum/msksum); wc = disc_w @ c
// ---------------------------------------------------------------------------
__global__ void __launch_bounds__(256) make_wc2(const float* __restrict__ disc_w) {
    __shared__ float red[4][64];
    __shared__ float cvec[64];
    __shared__ float msum_s;
    const int tid = threadIdx.x;
    const int g = tid >> 6, col = tid & 63;

    float s = 0.f;
#pragma unroll
    for (int b = 0; b < 16; ++b) s += g_part[(g * 16 + b) * 64 + col];
    red[g][col] = s;

    if (tid < 32) {
        float m = g_mskpart[tid] + g_mskpart[tid + 32];
#pragma unroll
        for (int o = 16; o; o >>= 1) m += __shfl_down_sync(0xffffffffu, m, o);
        if (tid == 0) msum_s = m;
    }
    __syncthreads();
    if (tid < 64) {
        float cv = (red[0][tid] + red[1][tid] + red[2][tid] + red[3][tid]) / msum_s;
        cvec[tid] = 1.f / (1.f + expf(-cv));
    }
    __syncthreads();

    const int j = tid >> 2, q = tid & 3;
    float r = 0.f;
#pragma unroll
    for (int k = 0; k < 16; ++k) r += disc_w[j * 64 + q * 16 + k] * cvec[q * 16 + k];
    r += __shfl_down_sync(0xffffffffu, r, 2);
    r += __shfl_down_sync(0xffffffffu, r, 1);
    if (q == 0) g_wc[j] = r;
}

// ---------------------------------------------------------------------------
// Kernel 6: out[n] = h1[n,:].wc + b ; out[N+n] = h2[n,:].wc + b
// ---------------------------------------------------------------------------
__global__ void __launch_bounds__(256) scores(const float* __restrict__ db,
                                              float* __restrict__ out) {
    const int warp = threadIdx.x >> 5, lane = threadIdx.x & 31;
    const int n = blockIdx.x * 8 + warp;
    const float2* hp = (const float2*)(g_h + (size_t)n * HC);
    const float2 w2 = ((const float2*)g_wc)[lane];
    const float2 v1 = hp[lane];
    const float2 v2 = hp[32 + lane];
    float s1 = v1.x * w2.x + v1.y * w2.y;
    float s2 = v2.x * w2.x + v2.y * w2.y;
#pragma unroll
    for (int o = 16; o; o >>= 1) {
        s1 += __shfl_down_sync(0xffffffffu, s1, o);
        s2 += __shfl_down_sync(0xffffffffu, s2, o);
    }
    if (lane == 0) {
        const float bb = __ldg(db);
        out[n] = s1 + bb;
        out[NN + n] = s2 + bb;
    }
}

// ---------------------------------------------------------------------------
// Inputs: seq1, seq2, adj, msk, fc_w, gcn_bias, prelu_alpha, disc_w, disc_b
// Output: [1, 2N] float32
// ---------------------------------------------------------------------------
extern "C" void kernel_launch(void* const* d_in, const int* in_sizes, int n_in,
                              void* d_out, int out_size) {
    const float* seq1  = (const float*)d_in[0];
    const float* seq2  = (const float*)d_in[1];
    const float* adj   = (const float*)d_in[2];
    const float* msk   = (const float*)d_in[3];
    const float* fcw   = (const float*)d_in[4];
    const float* gbias = (const float*)d_in[5];
    const float* alpha = (const float*)d_in[6];
    const float* discw = (const float*)d_in[7];
    const float* discb = (const float*)d_in[8];
    float* out = (float*)d_out;

    cudaFuncSetAttribute(gemm_mma, cudaFuncAttributeMaxDynamicSharedMemorySize,
                         DYN_SMEM);

    fts_kernel<<<NN / 16, 128>>>(seq1, seq2, fcw);
    gemm_mma<<<128, 256, DYN_SMEM>>>(adj);
    epi_kernel<<<NN * HC / 4 / 256, 256>>>(gbias, alpha);
    colsum_part<<<64, 256>>>(msk);
    make_wc2<<<1, 256>>>(discw);
    scores<<<NN / 8, 256>>>(discb, out);
}